// round 6
// baseline (speedup 1.0000x reference)
#include <cuda_runtime.h>
#include <cuda_fp16.h>
#include <math.h>

#define NN 50000
#define NE 800000
#define F  128
#define RPB 64        // rows per GEMM block
#define S   68        // hsT row stride (mult of 4 -> 16B-aligned row-pairs)

// ---------------- scratch (device globals; no allocation allowed) ----------
__device__ __align__(16) __half g_feath[NN * F];   // fp16 feat for the gather
__device__ __align__(16) float g_h1[NN * F];
__device__ __align__(16) float g_h2[NN * F];
__device__ __align__(16) float g_el[NN * 4];
__device__ __align__(16) float g_er[NN * 4];
__device__ int g_rowptr[NN + 1];
__device__ unsigned g_elmax_u[3][4];               // monotone-uint encoded per-layer/head max(el)

// ---------------- monotone float<->uint encode for atomicMax ---------------
__device__ __forceinline__ unsigned fenc(float f) {
    unsigned u = __float_as_uint(f);
    return (u & 0x80000000u) ? ~u : (u | 0x80000000u);
}
__device__ __forceinline__ float fdec(unsigned u) {
    return (u & 0x80000000u) ? __uint_as_float(u ^ 0x80000000u)
                             : __uint_as_float(~u);
}

// ---------------- f32x2 packed-math helpers --------------------------------
__device__ __forceinline__ unsigned long long pack2(float lo, float hi) {
    unsigned long long r;
    asm("mov.b64 %0, {%1, %2};" : "=l"(r) : "f"(lo), "f"(hi));
    return r;
}
__device__ __forceinline__ void unpack2(unsigned long long v, float& lo, float& hi) {
    asm("mov.b64 {%0, %1}, %2;" : "=f"(lo), "=f"(hi) : "l"(v));
}
__device__ __forceinline__ unsigned long long fma2(
    unsigned long long a, unsigned long long b, unsigned long long c) {
    unsigned long long d;
    asm("fma.rn.f32x2 %0, %1, %2, %3;" : "=l"(d) : "l"(a), "l"(b), "l"(c));
    return d;
}

// ---------------- init: reset elmax slots ----------------------------------
__global__ void init_elmax_kernel() {
    int i = threadIdx.x;
    if (i < 12) ((unsigned*)g_elmax_u)[i] = fenc(-3.0e38f);
}

// ---------------- row_ptr from sorted dst via lower_bound ------------------
__global__ void rowptr_kernel(const int* __restrict__ dst) {
    int n = blockIdx.x * blockDim.x + threadIdx.x;
    if (n > NN) return;
    int lo = 0, hi = NE;
    while (lo < hi) {
        int mid = (lo + hi) >> 1;
        if (dst[mid] < n) lo = mid + 1; else hi = mid;
    }
    g_rowptr[n] = lo;
}

// ---------------- per-head global max of el --------------------------------
__global__ __launch_bounds__(256) void elmax_kernel(int slot) {
    int n = blockIdx.x * blockDim.x + threadIdx.x;
    float4 v = (n < NN) ? *reinterpret_cast<const float4*>(&g_el[n * 4])
                        : make_float4(-3.0e38f, -3.0e38f, -3.0e38f, -3.0e38f);
    #pragma unroll
    for (int off = 16; off > 0; off >>= 1) {
        v.x = fmaxf(v.x, __shfl_xor_sync(0xffffffffu, v.x, off));
        v.y = fmaxf(v.y, __shfl_xor_sync(0xffffffffu, v.y, off));
        v.z = fmaxf(v.z, __shfl_xor_sync(0xffffffffu, v.z, off));
        v.w = fmaxf(v.w, __shfl_xor_sync(0xffffffffu, v.w, off));
    }
    if ((threadIdx.x & 31) == 0) {
        atomicMax(&g_elmax_u[slot][0], fenc(v.x));
        atomicMax(&g_elmax_u[slot][1], fenc(v.y));
        atomicMax(&g_elmax_u[slot][2], fenc(v.z));
        atomicMax(&g_elmax_u[slot][3], fenc(v.w));
    }
}

// ---------------- register-tiled GEMM (feat = h @ W) + el/er ---------------
// 64 rows x 128 cols per block, 128 threads (4 warps), 4 blocks/SM.
// Warp w owns rows 16w..16w+15 as 8 f32x2 row-pairs; lane owns cols
// 4*lane..4*lane+3. h tile transposed in shared with lane-consecutive
// (conflict-free) fill stores; row-pairs load as broadcast LDS.128.
__global__ __launch_bounds__(128, 4) void gemm_attn_kernel(
    const float* __restrict__ hin, const float* __restrict__ W,
    const float* __restrict__ al, const float* __restrict__ ar)
{
    __shared__ float hsT[F * S];           // 34.8 KB
    const int tid  = threadIdx.x;
    const int lane = tid & 31;
    const int w    = tid >> 5;
    const int base = blockIdx.x * RPB;

    // ---- fill transposed h tile: STS lane-consecutive -> conflict-free ----
    for (int k4 = w; k4 < 32; k4 += 4) {
        #pragma unroll
        for (int sub = 0; sub < 2; sub++) {
            int r = lane + 32 * sub;
            int n = base + r;
            float4 v = (n < NN)
                ? __ldg(reinterpret_cast<const float4*>(&hin[n * F + 4 * k4]))
                : make_float4(0.f, 0.f, 0.f, 0.f);
            hsT[(4 * k4 + 0) * S + r] = v.x;
            hsT[(4 * k4 + 1) * S + r] = v.y;
            hsT[(4 * k4 + 2) * S + r] = v.z;
            hsT[(4 * k4 + 3) * S + r] = v.w;
        }
    }
    __syncthreads();

    const int cg = lane;            // cols 4cg..4cg+3
    const int hb = 16 * w;          // rows hb..hb+15

    unsigned long long acc[8][4];
    #pragma unroll
    for (int rp = 0; rp < 8; rp++)
        #pragma unroll
        for (int c = 0; c < 4; c++) acc[rp][c] = 0ull;

    const float4* Wg = reinterpret_cast<const float4*>(W);

    #pragma unroll 2
    for (int k = 0; k < F; k++) {
        float4 wv = __ldg(&Wg[k * 32 + cg]);
        unsigned long long wp0 = pack2(wv.x, wv.x);
        unsigned long long wp1 = pack2(wv.y, wv.y);
        unsigned long long wp2 = pack2(wv.z, wv.z);
        unsigned long long wp3 = pack2(wv.w, wv.w);
        const ulonglong2* hp =
            reinterpret_cast<const ulonglong2*>(&hsT[k * S + hb]);
        #pragma unroll
        for (int q = 0; q < 4; q++) {       // 4 x ulonglong2 = 8 row-pairs
            ulonglong2 h2 = hp[q];          // broadcast LDS.128
            acc[2 * q + 0][0] = fma2(h2.x, wp0, acc[2 * q + 0][0]);
            acc[2 * q + 0][1] = fma2(h2.x, wp1, acc[2 * q + 0][1]);
            acc[2 * q + 0][2] = fma2(h2.x, wp2, acc[2 * q + 0][2]);
            acc[2 * q + 0][3] = fma2(h2.x, wp3, acc[2 * q + 0][3]);
            acc[2 * q + 1][0] = fma2(h2.y, wp0, acc[2 * q + 1][0]);
            acc[2 * q + 1][1] = fma2(h2.y, wp1, acc[2 * q + 1][1]);
            acc[2 * q + 1][2] = fma2(h2.y, wp2, acc[2 * q + 1][2]);
            acc[2 * q + 1][3] = fma2(h2.y, wp3, acc[2 * q + 1][3]);
        }
    }

    // ---- epilogue: fp16 feat + per-head el/er (fp32 exact) ----------------
    const float4 alv = *reinterpret_cast<const float4*>(&al[4 * cg]);
    const float4 arv = *reinterpret_cast<const float4*>(&ar[4 * cg]);
    const int head = cg >> 3;
    uint2* feath8 = reinterpret_cast<uint2*>(g_feath);

    #pragma unroll
    for (int rp = 0; rp < 8; rp++) {
        float a0[2], a1[2], a2[2], a3[2];
        unpack2(acc[rp][0], a0[0], a0[1]);
        unpack2(acc[rp][1], a1[0], a1[1]);
        unpack2(acc[rp][2], a2[0], a2[1]);
        unpack2(acc[rp][3], a3[0], a3[1]);
        #pragma unroll
        for (int rr = 0; rr < 2; rr++) {
            float sl = fmaf(a0[rr], alv.x, fmaf(a1[rr], alv.y,
                       fmaf(a2[rr], alv.z, a3[rr] * alv.w)));
            float sr = fmaf(a0[rr], arv.x, fmaf(a1[rr], arv.y,
                       fmaf(a2[rr], arv.z, a3[rr] * arv.w)));
            #pragma unroll
            for (int off = 1; off < 8; off <<= 1) {
                sl += __shfl_xor_sync(0xffffffffu, sl, off);
                sr += __shfl_xor_sync(0xffffffffu, sr, off);
            }
            int n = base + hb + 2 * rp + rr;
            if (n < NN) {
                __half2 p01 = __floats2half2_rn(a0[rr], a1[rr]);
                __half2 p23 = __floats2half2_rn(a2[rr], a3[rr]);
                uint2 pk;
                pk.x = *reinterpret_cast<unsigned*>(&p01);
                pk.y = *reinterpret_cast<unsigned*>(&p23);
                feath8[n * 32 + cg] = pk;
                if ((cg & 7) == 0) {
                    g_el[n * 4 + head] = sl;
                    g_er[n * 4 + head] = sr;
                }
            }
        }
    }
}

// ---------------- single-pass edge softmax + aggregation -------------------
// One warp per dst node. m = leaky(global_max(el)+er[n]) is a valid softmax
// shift (upper bound of all edge scores), so pass 1 is eliminated.
__global__ __launch_bounds__(256) void gat_agg_kernel(
    const int* __restrict__ src,
    const float* __restrict__ hres,   // residual input (may be null)
    float* __restrict__ out,
    int slot, int do_act, int do_mean)
{
    const int gw = (blockIdx.x * blockDim.x + threadIdx.x) >> 5;
    if (gw >= NN) return;
    const int lane = threadIdx.x & 31;
    const int n = gw;
    const int e0 = g_rowptr[n];
    const int e1 = g_rowptr[n + 1];
    const int head = lane >> 3;
    const float ern = g_er[n * 4 + head];
    float m = fdec(g_elmax_u[slot][head]) + ern;
    m = (m > 0.f) ? m : 0.2f * m;

    float ssum = 0.f;
    float4 acc = make_float4(0.f, 0.f, 0.f, 0.f);
    const uint2* feat8 = reinterpret_cast<const uint2*>(g_feath);
    #pragma unroll 4
    for (int i = e0; i < e1; i++) {
        int s = __ldg(&src[i]);
        float e = __ldg(&g_el[s * 4 + head]) + ern;
        e = (e > 0.f) ? e : 0.2f * e;          // leaky_relu(0.2)
        float wgt = __expf(e - m);
        ssum += wgt;
        uint2 pk = __ldg(&feat8[s * 32 + lane]);
        float2 f01 = __half22float2(*reinterpret_cast<__half2*>(&pk.x));
        float2 f23 = __half22float2(*reinterpret_cast<__half2*>(&pk.y));
        acc.x = fmaf(wgt, f01.x, acc.x);
        acc.y = fmaf(wgt, f01.y, acc.y);
        acc.z = fmaf(wgt, f23.x, acc.z);
        acc.w = fmaf(wgt, f23.y, acc.w);
    }

    float inv = (e1 > e0) ? (1.f / ssum) : 0.f;
    float4 o = make_float4(acc.x * inv, acc.y * inv, acc.z * inv, acc.w * inv);

    if (hres) {
        float4 r = __ldg(&reinterpret_cast<const float4*>(hres)[n * 32 + lane]);
        o.x += r.x; o.y += r.y; o.z += r.z; o.w += r.w;
    }
    if (do_act) {  // ELU(alpha=1)
        o.x = (o.x > 0.f) ? o.x : expm1f(o.x);
        o.y = (o.y > 0.f) ? o.y : expm1f(o.y);
        o.z = (o.z > 0.f) ? o.z : expm1f(o.z);
        o.w = (o.w > 0.f) ? o.w : expm1f(o.w);
    }

    if (do_mean) {
        o.x += __shfl_xor_sync(0xffffffffu, o.x, 8);
        o.y += __shfl_xor_sync(0xffffffffu, o.y, 8);
        o.z += __shfl_xor_sync(0xffffffffu, o.z, 8);
        o.w += __shfl_xor_sync(0xffffffffu, o.w, 8);
        o.x += __shfl_xor_sync(0xffffffffu, o.x, 16);
        o.y += __shfl_xor_sync(0xffffffffu, o.y, 16);
        o.z += __shfl_xor_sync(0xffffffffu, o.z, 16);
        o.w += __shfl_xor_sync(0xffffffffu, o.w, 16);
        if (lane < 8) {
            reinterpret_cast<float4*>(out)[n * 8 + lane] =
                make_float4(o.x * 0.25f, o.y * 0.25f, o.z * 0.25f, o.w * 0.25f);
        }
    } else {
        reinterpret_cast<float4*>(out)[n * 32 + lane] = o;
    }
}

// ---------------- launcher --------------------------------------------------
extern "C" void kernel_launch(void* const* d_in, const int* in_sizes, int n_in,
                              void* d_out, int out_size)
{
    const float* x   = (const float*)d_in[0];
    const int*   src = (const int*)d_in[1];
    const int*   dst = (const int*)d_in[2];
    const float* W0  = (const float*)d_in[3];
    const float* al0 = (const float*)d_in[4];
    const float* ar0 = (const float*)d_in[5];
    const float* W1  = (const float*)d_in[6];
    const float* al1 = (const float*)d_in[7];
    const float* ar1 = (const float*)d_in[8];
    const float* W2  = (const float*)d_in[9];
    const float* al2 = (const float*)d_in[10];
    const float* ar2 = (const float*)d_in[11];
    float* out = (float*)d_out;

    float *h1 = nullptr, *h2 = nullptr;
    cudaGetSymbolAddress((void**)&h1, g_h1);
    cudaGetSymbolAddress((void**)&h2, g_h2);

    const int gemm_grid = (NN + RPB - 1) / RPB;   // 782
    const int agg_grid  = (NN * 32) / 256;        // 6250 (exact)
    const int max_grid  = (NN + 255) / 256;       // 196

    init_elmax_kernel<<<1, 32>>>();
    rowptr_kernel<<<(NN + 1 + 255) / 256, 256>>>(dst);

    // layer 0: no residual, ELU
    gemm_attn_kernel<<<gemm_grid, 128>>>(x, W0, al0, ar0);
    elmax_kernel<<<max_grid, 256>>>(0);
    gat_agg_kernel<<<agg_grid, 256>>>(src, nullptr, h1, 0, /*act=*/1, /*mean=*/0);

    // layer 1: residual (input h1), ELU
    gemm_attn_kernel<<<gemm_grid, 128>>>(h1, W1, al1, ar1);
    elmax_kernel<<<max_grid, 256>>>(1);
    gat_agg_kernel<<<agg_grid, 256>>>(src, h1, h2, 1, /*act=*/1, /*mean=*/0);

    // layer 2: residual (input h2), no act, mean over heads -> [N, 32]
    gemm_attn_kernel<<<gemm_grid, 128>>>(h2, W2, al2, ar2);
    elmax_kernel<<<max_grid, 256>>>(2);
    gat_agg_kernel<<<agg_grid, 256>>>(src, h2, out, 2, /*act=*/0, /*mean=*/1);
}

// round 7
// speedup vs baseline: 1.1782x; 1.1782x over previous
#include <cuda_runtime.h>
#include <cuda_fp16.h>
#include <math.h>

#define NN 50000
#define NE 800000
#define F  128
#define RPB 64        // rows per GEMM block
#define S   68        // hsT row stride (mult of 4 -> 16B-aligned row-pairs)

// ---------------- scratch (device globals; no allocation allowed) ----------
__device__ __align__(16) __half g_feath[NN * F];   // fp16 feat for the gather
__device__ __align__(16) float g_h1[NN * F];
__device__ __align__(16) float g_h2[NN * F];
__device__ __align__(16) float g_el[NN * 4];
__device__ __align__(16) float g_er[NN * 4];
__device__ int g_rowptr[NN + 1];
__device__ unsigned g_elmax_u[3][4];   // monotone-uint per-layer/head max(el)

// ---------------- monotone float<->uint encode for atomicMax ---------------
__device__ __forceinline__ unsigned fenc(float f) {
    unsigned u = __float_as_uint(f);
    return (u & 0x80000000u) ? ~u : (u | 0x80000000u);
}
__device__ __forceinline__ float fdec(unsigned u) {
    return (u & 0x80000000u) ? __uint_as_float(u ^ 0x80000000u)
                             : __uint_as_float(~u);
}

// ---------------- f32x2 packed-math helpers --------------------------------
__device__ __forceinline__ unsigned long long pack2(float lo, float hi) {
    unsigned long long r;
    asm("mov.b64 %0, {%1, %2};" : "=l"(r) : "f"(lo), "f"(hi));
    return r;
}
__device__ __forceinline__ void unpack2(unsigned long long v, float& lo, float& hi) {
    asm("mov.b64 {%0, %1}, %2;" : "=f"(lo), "=f"(hi) : "l"(v));
}
__device__ __forceinline__ unsigned long long fma2(
    unsigned long long a, unsigned long long b, unsigned long long c) {
    unsigned long long d;
    asm("fma.rn.f32x2 %0, %1, %2, %3;" : "=l"(d) : "l"(a), "l"(b), "l"(c));
    return d;
}

// ---------------- row_ptr (sorted dst, lower_bound) + elmax reset ----------
__global__ void rowptr_kernel(const int* __restrict__ dst) {
    int n = blockIdx.x * blockDim.x + threadIdx.x;
    if (blockIdx.x == 0 && threadIdx.x < 12)
        ((unsigned*)g_elmax_u)[threadIdx.x] = fenc(-3.0e38f);
    if (n > NN) return;
    int lo = 0, hi = NE;
    while (lo < hi) {
        int mid = (lo + hi) >> 1;
        if (dst[mid] < n) lo = mid + 1; else hi = mid;
    }
    g_rowptr[n] = lo;
}

// ---------------- register-tiled GEMM (feat = h @ W) + el/er + elmax -------
// R4-winner shape: 64 rows x 128 cols per block, 256 threads, 2 blocks/SM.
// W cached whole in shared (64KB); h tile transposed (conflict-free fill);
// warp w owns rows 8w..8w+7 as 4 f32x2 pairs, lane owns 4 cols.
extern __shared__ float s_dyn[];

__global__ __launch_bounds__(256, 2) void gemm_attn_kernel(
    const float* __restrict__ hin, const float* __restrict__ W,
    const float* __restrict__ al, const float* __restrict__ ar, int slot)
{
    float* Wsh = s_dyn;                 // [128][128]
    float* hsT = s_dyn + F * F;         // [128][S] transposed h tile
    const int tid  = threadIdx.x;
    const int lane = tid & 31;
    const int w    = tid >> 5;
    const int base = blockIdx.x * RPB;

    // ---- load W (16384 floats, coalesced float4) ----
    {
        const float4* Wg  = reinterpret_cast<const float4*>(W);
        float4*       Ws4 = reinterpret_cast<float4*>(Wsh);
        #pragma unroll
        for (int i = 0; i < 16; i++) Ws4[tid + 256 * i] = Wg[tid + 256 * i];
    }
    // ---- fill transposed h tile: STS lane-consecutive -> conflict-free ----
    for (int k4 = w; k4 < 32; k4 += 8) {
        #pragma unroll
        for (int sub = 0; sub < 2; sub++) {
            int r = lane + 32 * sub;
            int n = base + r;
            float4 v = (n < NN)
                ? __ldg(reinterpret_cast<const float4*>(&hin[n * F + 4 * k4]))
                : make_float4(0.f, 0.f, 0.f, 0.f);
            hsT[(4 * k4 + 0) * S + r] = v.x;
            hsT[(4 * k4 + 1) * S + r] = v.y;
            hsT[(4 * k4 + 2) * S + r] = v.z;
            hsT[(4 * k4 + 3) * S + r] = v.w;
        }
    }
    __syncthreads();

    const int cg = lane;            // cols 4cg..4cg+3
    const int hb = 8 * w;           // rows hb..hb+7

    unsigned long long acc[4][4];   // [row-pair][col]
    #pragma unroll
    for (int rp = 0; rp < 4; rp++)
        #pragma unroll
        for (int c = 0; c < 4; c++) acc[rp][c] = 0ull;

    #pragma unroll 4
    for (int k = 0; k < F; k++) {
        float4 wv = *reinterpret_cast<const float4*>(&Wsh[k * F + 4 * cg]);
        unsigned long long wp0 = pack2(wv.x, wv.x);
        unsigned long long wp1 = pack2(wv.y, wv.y);
        unsigned long long wp2 = pack2(wv.z, wv.z);
        unsigned long long wp3 = pack2(wv.w, wv.w);
        const ulonglong2* hp =
            reinterpret_cast<const ulonglong2*>(&hsT[k * S + hb]);
        ulonglong2 hA = hp[0];     // rows (hb,hb+1),(hb+2,hb+3)
        ulonglong2 hB = hp[1];     // rows (hb+4,hb+5),(hb+6,hb+7)
        acc[0][0] = fma2(hA.x, wp0, acc[0][0]);
        acc[0][1] = fma2(hA.x, wp1, acc[0][1]);
        acc[0][2] = fma2(hA.x, wp2, acc[0][2]);
        acc[0][3] = fma2(hA.x, wp3, acc[0][3]);
        acc[1][0] = fma2(hA.y, wp0, acc[1][0]);
        acc[1][1] = fma2(hA.y, wp1, acc[1][1]);
        acc[1][2] = fma2(hA.y, wp2, acc[1][2]);
        acc[1][3] = fma2(hA.y, wp3, acc[1][3]);
        acc[2][0] = fma2(hB.x, wp0, acc[2][0]);
        acc[2][1] = fma2(hB.x, wp1, acc[2][1]);
        acc[2][2] = fma2(hB.x, wp2, acc[2][2]);
        acc[2][3] = fma2(hB.x, wp3, acc[2][3]);
        acc[3][0] = fma2(hB.y, wp0, acc[3][0]);
        acc[3][1] = fma2(hB.y, wp1, acc[3][1]);
        acc[3][2] = fma2(hB.y, wp2, acc[3][2]);
        acc[3][3] = fma2(hB.y, wp3, acc[3][3]);
    }

    // ---- epilogue: fp16 feat, per-head el/er, running elmax ---------------
    const float4 alv = *reinterpret_cast<const float4*>(&al[4 * cg]);
    const float4 arv = *reinterpret_cast<const float4*>(&ar[4 * cg]);
    const int head = cg >> 3;
    uint2* feath8 = reinterpret_cast<uint2*>(g_feath);
    float smax = -3.0e38f;

    #pragma unroll
    for (int rp = 0; rp < 4; rp++) {
        float a0[2], a1[2], a2[2], a3[2];
        unpack2(acc[rp][0], a0[0], a0[1]);
        unpack2(acc[rp][1], a1[0], a1[1]);
        unpack2(acc[rp][2], a2[0], a2[1]);
        unpack2(acc[rp][3], a3[0], a3[1]);
        #pragma unroll
        for (int rr = 0; rr < 2; rr++) {
            float sl = fmaf(a0[rr], alv.x, fmaf(a1[rr], alv.y,
                       fmaf(a2[rr], alv.z, a3[rr] * alv.w)));
            float sr = fmaf(a0[rr], arv.x, fmaf(a1[rr], arv.y,
                       fmaf(a2[rr], arv.z, a3[rr] * arv.w)));
            #pragma unroll
            for (int off = 1; off < 8; off <<= 1) {
                sl += __shfl_xor_sync(0xffffffffu, sl, off);
                sr += __shfl_xor_sync(0xffffffffu, sr, off);
            }
            int n = base + hb + 2 * rp + rr;
            if (n < NN) {
                __half2 p01 = __floats2half2_rn(a0[rr], a1[rr]);
                __half2 p23 = __floats2half2_rn(a2[rr], a3[rr]);
                uint2 pk;
                pk.x = *reinterpret_cast<unsigned*>(&p01);
                pk.y = *reinterpret_cast<unsigned*>(&p23);
                feath8[n * 32 + cg] = pk;
                smax = fmaxf(smax, sl);
                if ((cg & 7) == 0) {
                    g_el[n * 4 + head] = sl;
                    g_er[n * 4 + head] = sr;
                }
            }
        }
    }
    if ((cg & 7) == 0) atomicMax(&g_elmax_u[slot][head], fenc(smax));
}

// ---------------- single-pass edge softmax + aggregation -------------------
// One warp per dst node. m = leaky(global_max(el)+er[n]) is a valid shift.
// Lanes cooperatively load a 32-edge src window (coalesced), then an
// 8-unrolled inner loop broadcasts s via shfl -> el/feat loads batch (MLP 8).
__global__ __launch_bounds__(256) void gat_agg_kernel(
    const int* __restrict__ src,
    const float* __restrict__ hres,   // residual input (may be null)
    float* __restrict__ out,
    int slot, int do_act, int do_mean)
{
    const int gw = (blockIdx.x * blockDim.x + threadIdx.x) >> 5;
    if (gw >= NN) return;
    const int lane = threadIdx.x & 31;
    const int n = gw;
    const int e0 = g_rowptr[n];
    const int e1 = g_rowptr[n + 1];
    const int head = lane >> 3;
    const float ern = g_er[n * 4 + head];
    float m = fdec(g_elmax_u[slot][head]) + ern;
    m = (m > 0.f) ? m : 0.2f * m;

    float ssum = 0.f;
    float4 acc = make_float4(0.f, 0.f, 0.f, 0.f);
    const uint2* feat8 = reinterpret_cast<const uint2*>(g_feath);

    for (int basee = e0; basee < e1; basee += 32) {
        int idx = basee + lane;
        int sw = (idx < e1) ? __ldg(&src[idx]) : 0;   // pad -> node 0 (valid)
        int lim = e1 - basee;
        if (lim > 32) lim = 32;
        for (int c = 0; c < lim; c += 8) {
            #pragma unroll
            for (int j = 0; j < 8; j++) {
                int jj = c + j;
                int s = __shfl_sync(0xffffffffu, sw, jj);
                float e = __ldg(&g_el[s * 4 + head]) + ern;
                e = (e > 0.f) ? e : 0.2f * e;          // leaky_relu(0.2)
                float wgt = (jj < lim) ? __expf(e - m) : 0.f;
                ssum += wgt;
                uint2 pk = __ldg(&feat8[s * 32 + lane]);
                float2 f01 = __half22float2(*reinterpret_cast<__half2*>(&pk.x));
                float2 f23 = __half22float2(*reinterpret_cast<__half2*>(&pk.y));
                acc.x = fmaf(wgt, f01.x, acc.x);
                acc.y = fmaf(wgt, f01.y, acc.y);
                acc.z = fmaf(wgt, f23.x, acc.z);
                acc.w = fmaf(wgt, f23.y, acc.w);
            }
        }
    }

    float inv = (e1 > e0) ? (1.f / ssum) : 0.f;
    float4 o = make_float4(acc.x * inv, acc.y * inv, acc.z * inv, acc.w * inv);

    if (hres) {
        float4 r = __ldg(&reinterpret_cast<const float4*>(hres)[n * 32 + lane]);
        o.x += r.x; o.y += r.y; o.z += r.z; o.w += r.w;
    }
    if (do_act) {  // ELU(alpha=1)
        o.x = (o.x > 0.f) ? o.x : expm1f(o.x);
        o.y = (o.y > 0.f) ? o.y : expm1f(o.y);
        o.z = (o.z > 0.f) ? o.z : expm1f(o.z);
        o.w = (o.w > 0.f) ? o.w : expm1f(o.w);
    }

    if (do_mean) {
        o.x += __shfl_xor_sync(0xffffffffu, o.x, 8);
        o.y += __shfl_xor_sync(0xffffffffu, o.y, 8);
        o.z += __shfl_xor_sync(0xffffffffu, o.z, 8);
        o.w += __shfl_xor_sync(0xffffffffu, o.w, 8);
        o.x += __shfl_xor_sync(0xffffffffu, o.x, 16);
        o.y += __shfl_xor_sync(0xffffffffu, o.y, 16);
        o.z += __shfl_xor_sync(0xffffffffu, o.z, 16);
        o.w += __shfl_xor_sync(0xffffffffu, o.w, 16);
        if (lane < 8) {
            reinterpret_cast<float4*>(out)[n * 8 + lane] =
                make_float4(o.x * 0.25f, o.y * 0.25f, o.z * 0.25f, o.w * 0.25f);
        }
    } else {
        reinterpret_cast<float4*>(out)[n * 32 + lane] = o;
    }
}

// ---------------- launcher --------------------------------------------------
extern "C" void kernel_launch(void* const* d_in, const int* in_sizes, int n_in,
                              void* d_out, int out_size)
{
    const float* x   = (const float*)d_in[0];
    const int*   src = (const int*)d_in[1];
    const int*   dst = (const int*)d_in[2];
    const float* W0  = (const float*)d_in[3];
    const float* al0 = (const float*)d_in[4];
    const float* ar0 = (const float*)d_in[5];
    const float* W1  = (const float*)d_in[6];
    const float* al1 = (const float*)d_in[7];
    const float* ar1 = (const float*)d_in[8];
    const float* W2  = (const float*)d_in[9];
    const float* al2 = (const float*)d_in[10];
    const float* ar2 = (const float*)d_in[11];
    float* out = (float*)d_out;

    float *h1 = nullptr, *h2 = nullptr;
    cudaGetSymbolAddress((void**)&h1, g_h1);
    cudaGetSymbolAddress((void**)&h2, g_h2);

    const int smem_bytes = (F * F + F * S) * sizeof(float);  // ~98KB
    static int smem_set = 0;
    if (!smem_set) {
        cudaFuncSetAttribute(gemm_attn_kernel,
                             cudaFuncAttributeMaxDynamicSharedMemorySize, smem_bytes);
        smem_set = 1;
    }

    const int gemm_grid = (NN + RPB - 1) / RPB;   // 782
    const int agg_grid  = (NN * 32) / 256;        // 6250 (exact)

    rowptr_kernel<<<(NN + 1 + 255) / 256, 256>>>(dst);

    // layer 0: no residual, ELU
    gemm_attn_kernel<<<gemm_grid, 256, smem_bytes>>>(x, W0, al0, ar0, 0);
    gat_agg_kernel<<<agg_grid, 256>>>(src, nullptr, h1, 0, /*act=*/1, /*mean=*/0);

    // layer 1: residual (input h1), ELU
    gemm_attn_kernel<<<gemm_grid, 256, smem_bytes>>>(h1, W1, al1, ar1, 1);
    gat_agg_kernel<<<agg_grid, 256>>>(src, h1, h2, 1, /*act=*/1, /*mean=*/0);

    // layer 2: residual (input h2), no act, mean over heads -> [N, 32]
    gemm_attn_kernel<<<gemm_grid, 256, smem_bytes>>>(h2, W2, al2, ar2, 2);
    gat_agg_kernel<<<agg_grid, 256>>>(src, h2, out, 2, /*act=*/0, /*mean=*/1);
}